// round 6
// baseline (speedup 1.0000x reference)
#include <cuda_runtime.h>

static constexpr int NN = 50000;
static constexpr int EE = 800000;

typedef unsigned long long u64;

__device__ __forceinline__ u64 fma2(u64 a, u64 b, u64 c) {
    u64 d;
    asm("fma.rn.f32x2 %0, %1, %2, %3;" : "=l"(d) : "l"(a), "l"(b), "l"(c));
    return d;
}
__device__ __forceinline__ float2 unpack2(u64 v) {
    float2 f;
    asm("mov.b64 {%0,%1}, %2;" : "=f"(f.x), "=f"(f.y) : "l"(v));
    return f;
}

// ---------------- scratch (device globals; no allocation allowed) ----------
__device__ float g_h[NN * 128];      // pre-aggregation features (act(A) @ W)
__device__ float g_agg[NN * 128];    // aggregated features
__device__ float g_deg[NN];
__device__ float g_dinv[NN];
__device__ int   g_cnt[NN];
__device__ int   g_rank[EE];         // edge's arrival rank within its dst bucket
__device__ int   g_rowptr[NN + 1];
__device__ int2  g_csr[EE];          // {src, __float_as_int(coef)}
// [0,256): layer1 sum/sumsq, [256,512): layer2 sum/sumsq,
// [512,768): layer1 scale/shift, [768,1024): layer2 scale/shift
__device__ float g_stats[1024];

// ---------------- CSR build ------------------------------------------------
__global__ void k_init() {
    int i = blockIdx.x * 256 + threadIdx.x;
    if (i < NN) { g_deg[i] = 1.0f; g_cnt[i] = 0; }
    if (i < 1024) g_stats[i] = 0.0f;
}

__global__ void k_count(const int* __restrict__ dst, const float* __restrict__ ew) {
    int e = blockIdx.x * 256 + threadIdx.x;
    if (e < EE) {
        int d = dst[e];
        int r = atomicAdd(&g_cnt[d], 1);
        g_rank[e] = r;
        atomicAdd(&g_deg[d], ew[e]);
    }
}

__global__ void k_scan() {
    const int tid = threadIdx.x;
    __shared__ int warp_sums[32];
    __shared__ int s_carry;
    if (tid == 0) s_carry = 0;
    __syncthreads();
    for (int base = 0; base < NN; base += 1024) {
        int i = base + tid;
        int v = (i < NN) ? g_cnt[i] : 0;
        int x = v;
        #pragma unroll
        for (int o = 1; o < 32; o <<= 1) {
            int t = __shfl_up_sync(0xffffffffu, x, o);
            if ((tid & 31) >= o) x += t;
        }
        if ((tid & 31) == 31) warp_sums[tid >> 5] = x;
        __syncthreads();
        if (tid < 32) {
            int w = warp_sums[tid];
            #pragma unroll
            for (int o = 1; o < 32; o <<= 1) {
                int t = __shfl_up_sync(0xffffffffu, w, o);
                if (tid >= o) w += t;
            }
            warp_sums[tid] = w;
        }
        __syncthreads();
        int woff = (tid >= 32) ? warp_sums[(tid >> 5) - 1] : 0;
        int incl = x + woff;
        int carry = s_carry;
        if (i < NN) {
            g_rowptr[i] = carry + incl - v;   // exclusive
            g_dinv[i] = rsqrtf(g_deg[i]);     // deg >= 1 always (self loop)
        }
        __syncthreads();
        if (tid == 1023) s_carry = carry + incl;
        __syncthreads();
    }
    if (tid == 0) g_rowptr[NN] = s_carry;
}

// atomic-free: slot = rowptr[d] + rank[e]
__global__ void k_fill(const int* __restrict__ src, const int* __restrict__ dst,
                       const float* __restrict__ ew) {
    int e = blockIdx.x * 256 + threadIdx.x;
    if (e < EE) {
        int s = src[e], d = dst[e];
        int pos = g_rowptr[d] + g_rank[e];
        float c = g_dinv[s] * ew[e] * g_dinv[d];
        g_csr[pos] = make_int2(s, __float_as_int(c));
    }
}

// ---------------- GEMM: g_h = act(A) @ W  (K = 128, packed f32x2) ----------
// If coff >= 0, applies relu(v*scale+shift) to A on load (prev layer BN+ReLU).
// If Aext == nullptr, reads g_agg.
template <int BN>
__global__ void __launch_bounds__(256, 2)
k_gemm(const float* __restrict__ Aext, const float* __restrict__ Wm, int coff) {
    constexpr int CG = BN / 8;     // col groups (16 or 8)
    constexpr int RG = 256 / CG;   // row groups (16 or 32)
    constexpr int BM = RG * 8;     // tile rows (128 or 256)
    constexpr int BK = 16;
    __shared__ float  As[BK][BM + 4];
    __shared__ float2 Bs2[BK][8][CG];   // [k][j][cg], value duplicated {b,b}
    const float* A = Aext ? Aext : g_agg;
    const int tid = threadIdx.x;
    const int row_base = blockIdx.x * BM;
    const int rg = tid / CG, cg = tid % CG;

    u64 acc[4][8];   // [row-pair][col]; rows rg*8+2i, rg*8+2i+1; col cg*8+j
    #pragma unroll
    for (int i = 0; i < 4; i++)
        #pragma unroll
        for (int j = 0; j < 8; j++) acc[i][j] = 0ull;

    for (int k0 = 0; k0 < 128; k0 += BK) {
        // A tile (transposed into As[k][row]) with fused BN+ReLU
        #pragma unroll
        for (int i = tid; i < BM * 4; i += 256) {
            int r = i >> 2;
            int kk = (i & 3) << 2;
            int gr = row_base + r;
            float4 v = make_float4(0.f, 0.f, 0.f, 0.f);
            if (gr < NN) {
                v = *(const float4*)(A + gr * 128 + k0 + kk);
                if (coff >= 0) {
                    float4 sc = *(const float4*)(g_stats + coff + k0 + kk);
                    float4 sh = *(const float4*)(g_stats + coff + 128 + k0 + kk);
                    v.x = fmaxf(0.f, fmaf(v.x, sc.x, sh.x));
                    v.y = fmaxf(0.f, fmaf(v.y, sc.y, sh.y));
                    v.z = fmaxf(0.f, fmaf(v.z, sc.z, sh.z));
                    v.w = fmaxf(0.f, fmaf(v.w, sc.w, sh.w));
                }
            }
            As[kk + 0][r] = v.x; As[kk + 1][r] = v.y;
            As[kk + 2][r] = v.z; As[kk + 3][r] = v.w;
        }
        // W tile, duplicated into Bs2[kk][j][cg]
        #pragma unroll
        for (int i = tid; i < BK * (BN / 4); i += 256) {
            int kk = i / (BN / 4);
            int c = (i % (BN / 4)) << 2;   // multiple of 4
            float4 wv = *(const float4*)(Wm + (k0 + kk) * BN + c);
            int jb = c & 7, cc = c >> 3;
            Bs2[kk][jb + 0][cc] = make_float2(wv.x, wv.x);
            Bs2[kk][jb + 1][cc] = make_float2(wv.y, wv.y);
            Bs2[kk][jb + 2][cc] = make_float2(wv.z, wv.z);
            Bs2[kk][jb + 3][cc] = make_float2(wv.w, wv.w);
        }
        __syncthreads();
        #pragma unroll
        for (int kk = 0; kk < BK; kk++) {
            u64 a2[4], b2[8];
            #pragma unroll
            for (int i = 0; i < 4; i++)
                a2[i] = *(const u64*)&As[kk][rg * 8 + 2 * i];
            #pragma unroll
            for (int j = 0; j < 8; j++)
                b2[j] = *(const u64*)&Bs2[kk][j][cg];
            #pragma unroll
            for (int i = 0; i < 4; i++)
                #pragma unroll
                for (int j = 0; j < 8; j++)
                    acc[i][j] = fma2(a2[i], b2[j], acc[i][j]);
        }
        __syncthreads();
    }
    #pragma unroll
    for (int i = 0; i < 4; i++) {
        int r0 = row_base + rg * 8 + 2 * i;
        float lo[8], hi[8];
        #pragma unroll
        for (int j = 0; j < 8; j++) {
            float2 v = unpack2(acc[i][j]);
            lo[j] = v.x; hi[j] = v.y;
        }
        if (r0 < NN) {
            *(float4*)(g_h + r0 * BN + cg * 8)     = make_float4(lo[0], lo[1], lo[2], lo[3]);
            *(float4*)(g_h + r0 * BN + cg * 8 + 4) = make_float4(lo[4], lo[5], lo[6], lo[7]);
        }
        if (r0 + 1 < NN) {
            *(float4*)(g_h + (r0 + 1) * BN + cg * 8)     = make_float4(hi[0], hi[1], hi[2], hi[3]);
            *(float4*)(g_h + (r0 + 1) * BN + cg * 8 + 4) = make_float4(hi[4], hi[5], hi[6], hi[7]);
        }
    }
}

// ---------------- aggregation + fused BN stats -----------------------------
// out[n] = b + dinv[n]^2 h[n] + sum coef*h[src]; if statsoff>=0 also
// accumulates per-column sum/sumsq of the output into g_stats[statsoff..].
__global__ void __launch_bounds__(256)
k_agg128(const float* __restrict__ bias, float* __restrict__ outp, int statsoff) {
    __shared__ float4 s_sum[8][32];
    __shared__ float4 s_sq[8][32];
    int wlocal = threadIdx.x >> 5;
    int w = (blockIdx.x * 256 + threadIdx.x) >> 5;
    int lane = threadIdx.x & 31;
    const float4* h4 = (const float4*)g_h;
    float4 b4 = ((const float4*)bias)[lane];
    float4 sf = h4[w * 32 + lane];
    float di = g_dinv[w];
    float sc = di * di;
    float4 acc;
    acc.x = fmaf(sc, sf.x, b4.x);
    acc.y = fmaf(sc, sf.y, b4.y);
    acc.z = fmaf(sc, sf.z, b4.z);
    acc.w = fmaf(sc, sf.w, b4.w);
    int e = g_rowptr[w];
    const int end = g_rowptr[w + 1];
    for (; e + 2 <= end; e += 2) {
        int2 p0 = g_csr[e], p1 = g_csr[e + 1];
        float4 v0 = h4[p0.x * 32 + lane];
        float4 v1 = h4[p1.x * 32 + lane];
        float c0 = __int_as_float(p0.y), c1 = __int_as_float(p1.y);
        acc.x = fmaf(c0, v0.x, acc.x); acc.y = fmaf(c0, v0.y, acc.y);
        acc.z = fmaf(c0, v0.z, acc.z); acc.w = fmaf(c0, v0.w, acc.w);
        acc.x = fmaf(c1, v1.x, acc.x); acc.y = fmaf(c1, v1.y, acc.y);
        acc.z = fmaf(c1, v1.z, acc.z); acc.w = fmaf(c1, v1.w, acc.w);
    }
    if (e < end) {
        int2 p = g_csr[e];
        float4 v = h4[p.x * 32 + lane];
        float c = __int_as_float(p.y);
        acc.x = fmaf(c, v.x, acc.x); acc.y = fmaf(c, v.y, acc.y);
        acc.z = fmaf(c, v.z, acc.z); acc.w = fmaf(c, v.w, acc.w);
    }
    float4* o4 = (float4*)(outp ? outp : g_agg);
    o4[w * 32 + lane] = acc;

    if (statsoff >= 0) {
        s_sum[wlocal][lane] = acc;
        s_sq[wlocal][lane] = make_float4(acc.x * acc.x, acc.y * acc.y,
                                         acc.z * acc.z, acc.w * acc.w);
        __syncthreads();
        if (threadIdx.x < 128) {
            int c = threadIdx.x;         // column 0..127
            int l = c >> 2, comp = c & 3;
            float s = 0.f, q = 0.f;
            #pragma unroll
            for (int ww = 0; ww < 8; ww++) {
                const float* ps = (const float*)&s_sum[ww][l];
                const float* pq = (const float*)&s_sq[ww][l];
                s += ps[comp];
                q += pq[comp];
            }
            atomicAdd(&g_stats[statsoff + c], s);
            atomicAdd(&g_stats[statsoff + 128 + c], q);
        }
    }
}

__global__ void __launch_bounds__(256)
k_agg64(const float* __restrict__ bias, float* __restrict__ outp) {
    int w = (blockIdx.x * 256 + threadIdx.x) >> 5;
    int lane = threadIdx.x & 31;
    const float2* h2 = (const float2*)g_h;   // g_h interpreted as [NN][64]
    float2 b2v = ((const float2*)bias)[lane];
    float2 sf = h2[w * 32 + lane];
    float di = g_dinv[w];
    float sc = di * di;
    float2 acc;
    acc.x = fmaf(sc, sf.x, b2v.x);
    acc.y = fmaf(sc, sf.y, b2v.y);
    int e = g_rowptr[w];
    const int end = g_rowptr[w + 1];
    for (; e + 2 <= end; e += 2) {
        int2 p0 = g_csr[e], p1 = g_csr[e + 1];
        float2 v0 = h2[p0.x * 32 + lane];
        float2 v1 = h2[p1.x * 32 + lane];
        float c0 = __int_as_float(p0.y), c1 = __int_as_float(p1.y);
        acc.x = fmaf(c0, v0.x, acc.x); acc.y = fmaf(c0, v0.y, acc.y);
        acc.x = fmaf(c1, v1.x, acc.x); acc.y = fmaf(c1, v1.y, acc.y);
    }
    if (e < end) {
        int2 p = g_csr[e];
        float2 v = h2[p.x * 32 + lane];
        float c = __int_as_float(p.y);
        acc.x = fmaf(c, v.x, acc.x); acc.y = fmaf(c, v.y, acc.y);
    }
    ((float2*)outp)[w * 32 + lane] = acc;
}

// ---------------- BN finalize ----------------------------------------------
__global__ void k_bnfin(int soff, int coff, const float* __restrict__ gamma,
                        const float* __restrict__ beta) {
    int c = threadIdx.x;
    if (c < 128) {
        float mean = g_stats[soff + c] * (1.0f / NN);
        float var = g_stats[soff + 128 + c] * (1.0f / NN) - mean * mean;
        float rstd = rsqrtf(var + 1e-5f);
        float sc = rstd * gamma[c];
        g_stats[coff + c] = sc;
        g_stats[coff + 128 + c] = beta[c] - mean * sc;
    }
}

// ---------------- launch ----------------------------------------------------
extern "C" void kernel_launch(void* const* d_in, const int* in_sizes, int n_in,
                              void* d_out, int out_size) {
    const float* x   = (const float*)d_in[0];
    const int*   ei  = (const int*)d_in[1];
    const float* ew  = (const float*)d_in[2];
    const float* W1  = (const float*)d_in[3];
    const float* b1  = (const float*)d_in[4];
    const float* W2  = (const float*)d_in[5];
    const float* b2  = (const float*)d_in[6];
    const float* W3  = (const float*)d_in[7];
    const float* b3  = (const float*)d_in[8];
    const float* g1  = (const float*)d_in[9];
    const float* be1 = (const float*)d_in[10];
    const float* g2  = (const float*)d_in[11];
    const float* be2 = (const float*)d_in[12];
    const int* src = ei;
    const int* dst = ei + EE;
    float* out = (float*)d_out;

    const int agg_blocks = (NN * 32) / 256;        // 6250 exact
    const int edge_blocks = (EE + 255) / 256;      // 3125

    // graph normalization + CSR (shared by all 3 layers)
    k_init<<<(NN + 255) / 256, 256>>>();
    k_count<<<edge_blocks, 256>>>(dst, ew);
    k_scan<<<1, 1024>>>();
    k_fill<<<edge_blocks, 256>>>(src, dst, ew);

    // layer 1
    k_gemm<128><<<(NN + 127) / 128, 256>>>(x, W1, -1);
    k_agg128<<<agg_blocks, 256>>>(b1, nullptr, 0);
    k_bnfin<<<1, 128>>>(0, 512, g1, be1);

    // layer 2 (BN+ReLU of layer1 fused into A-load)
    k_gemm<128><<<(NN + 127) / 128, 256>>>(nullptr, W2, 512);
    k_agg128<<<agg_blocks, 256>>>(b2, nullptr, 256);
    k_bnfin<<<1, 128>>>(256, 768, g2, be2);

    // layer 3 (64-wide output; BN+ReLU of layer2 fused into A-load)
    k_gemm<64><<<(NN + 255) / 256, 256>>>(nullptr, W3, 768);
    k_agg64<<<agg_blocks, 256>>>(b3, out);
}

// round 9
// speedup vs baseline: 1.1270x; 1.1270x over previous
#include <cuda_runtime.h>
#include <cuda_bf16.h>
#include <cstdint>

static constexpr int NN = 50000;
static constexpr int EE = 800000;

// ---------------- scratch (device globals; no allocation allowed) ----------
__device__ float g_h[NN * 128];      // pre-aggregation features (act(A) @ W)
__device__ float g_agg[NN * 128];    // aggregated features
__device__ float g_deg[NN];
__device__ float g_dinv[NN];
__device__ int   g_cnt[NN];
__device__ int   g_rank[EE];
__device__ int   g_rowptr[NN + 1];
__device__ int2  g_csr[EE];          // {src, __float_as_int(coef)}
__device__ float g_stats[1024];
// W transposed [N][K] bf16 hi/lo: W1hi@0 W1lo@16384 W2hi@32768 W2lo@49152 W3hi@65536 W3lo@73728
__device__ __align__(16) __nv_bfloat16 g_wblk[81920];

__device__ __forceinline__ uint32_t packbf2(float x, float y) {
    __nv_bfloat162 p = __floats2bfloat162_rn(x, y);
    return *(uint32_t*)&p;
}

#define MMA_BF16(d, a, b) \
    asm volatile("mma.sync.aligned.m16n8k16.row.col.f32.bf16.bf16.f32 " \
        "{%0,%1,%2,%3}, {%4,%5,%6,%7}, {%8,%9}, {%0,%1,%2,%3};" \
        : "+f"((d)[0]), "+f"((d)[1]), "+f"((d)[2]), "+f"((d)[3]) \
        : "r"((a)[0]), "r"((a)[1]), "r"((a)[2]), "r"((a)[3]), "r"((b)[0]), "r"((b)[1]))

// ---------------- CSR build (unchanged, known-good) -------------------------
__global__ void k_init() {
    int i = blockIdx.x * 256 + threadIdx.x;
    if (i < NN) { g_deg[i] = 1.0f; g_cnt[i] = 0; }
    if (i < 1024) g_stats[i] = 0.0f;
}
__global__ void k_count(const int* __restrict__ dst, const float* __restrict__ ew) {
    int e = blockIdx.x * 256 + threadIdx.x;
    if (e < EE) {
        int d = dst[e];
        g_rank[e] = atomicAdd(&g_cnt[d], 1);
        atomicAdd(&g_deg[d], ew[e]);
    }
}
__global__ void k_scan() {
    const int tid = threadIdx.x;
    __shared__ int warp_sums[32];
    __shared__ int s_carry;
    if (tid == 0) s_carry = 0;
    __syncthreads();
    for (int base = 0; base < NN; base += 1024) {
        int i = base + tid;
        int v = (i < NN) ? g_cnt[i] : 0;
        int x = v;
        #pragma unroll
        for (int o = 1; o < 32; o <<= 1) {
            int t = __shfl_up_sync(0xffffffffu, x, o);
            if ((tid & 31) >= o) x += t;
        }
        if ((tid & 31) == 31) warp_sums[tid >> 5] = x;
        __syncthreads();
        if (tid < 32) {
            int w = warp_sums[tid];
            #pragma unroll
            for (int o = 1; o < 32; o <<= 1) {
                int t = __shfl_up_sync(0xffffffffu, w, o);
                if (tid >= o) w += t;
            }
            warp_sums[tid] = w;
        }
        __syncthreads();
        int woff = (tid >= 32) ? warp_sums[(tid >> 5) - 1] : 0;
        int incl = x + woff;
        int carry = s_carry;
        if (i < NN) {
            g_rowptr[i] = carry + incl - v;
            g_dinv[i] = rsqrtf(g_deg[i]);
        }
        __syncthreads();
        if (tid == 1023) s_carry = carry + incl;
        __syncthreads();
    }
    if (tid == 0) g_rowptr[NN] = s_carry;
}
__global__ void k_fill(const int* __restrict__ src, const int* __restrict__ dst,
                       const float* __restrict__ ew) {
    int e = blockIdx.x * 256 + threadIdx.x;
    if (e < EE) {
        int s = src[e], d = dst[e];
        int pos = g_rowptr[d] + g_rank[e];
        float c = g_dinv[s] * ew[e] * g_dinv[d];
        g_csr[pos] = make_int2(s, __float_as_int(c));
    }
}

// ---------------- W prep: fp32 [K=128][N] -> transposed [N][128] bf16 hi/lo -
__device__ __forceinline__ void prep_one(const float* W, int N, int t,
                                         __nv_bfloat16* hi_d, __nv_bfloat16* lo_d) {
    int k = t / N, n = t % N;
    float w = W[k * N + n];
    __nv_bfloat16 h = __float2bfloat16(w);
    __nv_bfloat16 l = __float2bfloat16(w - __bfloat162float(h));
    hi_d[n * 128 + k] = h;
    lo_d[n * 128 + k] = l;
}
__global__ void k_prepw(const float* __restrict__ W1, const float* __restrict__ W2,
                        const float* __restrict__ W3) {
    int b = blockIdx.x, tid = threadIdx.x;
    if (b < 64)        prep_one(W1, 128, b * 256 + tid,         g_wblk,         g_wblk + 16384);
    else if (b < 128)  prep_one(W2, 128, (b - 64) * 256 + tid,  g_wblk + 32768, g_wblk + 49152);
    else               prep_one(W3, 64,  (b - 128) * 256 + tid, g_wblk + 65536, g_wblk + 73728);
}

// ---------------- GEMM: g_h = act(A) @ W via mma.sync bf16 3-term -----------
// smem: Ahi/Alo [128][KP], Wthi/Wtlo [BN][KP] bf16, KP=136 (conflict-free pad)
template <int BN>
__global__ void __launch_bounds__(256, 1)
k_gemm_mma(const float* __restrict__ Aext, int coff,
           const __nv_bfloat16* __restrict__ whi, const __nv_bfloat16* __restrict__ wlo) {
    constexpr int KP = 136;
    constexpr int NT = BN / 16;              // n8-tiles per warp (8 or 4)
    constexpr int A_HI = 0;
    constexpr int A_LO = 128 * KP * 2;       // 34816
    constexpr int W_HI = 2 * 128 * KP * 2;   // 69632
    constexpr int W_LO = W_HI + BN * KP * 2;
    extern __shared__ char smem[];
    const float* A = Aext ? Aext : g_agg;
    const int tid = threadIdx.x;
    const int wid = tid >> 5, lane = tid & 31;
    const int warp_m = wid & 3, warp_n = wid >> 2;
    const int row_base = blockIdx.x * 128;

    // stage A (convert fp32 -> bf16 hi/lo, fused BN+ReLU)
    for (int i = tid; i < 128 * 32; i += 256) {
        int r = i >> 5;
        int c = (i & 31) << 2;
        int gr = row_base + r;
        float4 v = make_float4(0.f, 0.f, 0.f, 0.f);
        if (gr < NN) {
            v = *(const float4*)(A + (long)gr * 128 + c);
            if (coff >= 0) {
                float4 sc = *(const float4*)(g_stats + coff + c);
                float4 sh = *(const float4*)(g_stats + coff + 128 + c);
                v.x = fmaxf(0.f, fmaf(v.x, sc.x, sh.x));
                v.y = fmaxf(0.f, fmaf(v.y, sc.y, sh.y));
                v.z = fmaxf(0.f, fmaf(v.z, sc.z, sh.z));
                v.w = fmaxf(0.f, fmaf(v.w, sc.w, sh.w));
            }
        }
        float hx = __bfloat162float(__float2bfloat16(v.x));
        float hy = __bfloat162float(__float2bfloat16(v.y));
        float hz = __bfloat162float(__float2bfloat16(v.z));
        float hw = __bfloat162float(__float2bfloat16(v.w));
        uint32_t off = (r * KP + c) * 2;
        *(uint32_t*)(smem + A_HI + off)     = packbf2(hx, hy);
        *(uint32_t*)(smem + A_HI + off + 4) = packbf2(hz, hw);
        *(uint32_t*)(smem + A_LO + off)     = packbf2(v.x - hx, v.y - hy);
        *(uint32_t*)(smem + A_LO + off + 4) = packbf2(v.z - hz, v.w - hw);
    }
    // stage Wt (pre-transposed global, 16B chunks; KP pad preserved)
    for (int i = tid; i < BN * 16; i += 256) {
        int n = i >> 4;
        int k = (i & 15) << 3;
        uint32_t off = (n * KP + k) * 2;
        *(uint4*)(smem + W_HI + off) = ((const uint4*)whi)[i];
        *(uint4*)(smem + W_LO + off) = ((const uint4*)wlo)[i];
    }
    __syncthreads();

    const int g = lane >> 2, tg = lane & 3;
    float acc[2][NT][4];
    #pragma unroll
    for (int mt = 0; mt < 2; mt++)
        #pragma unroll
        for (int nt = 0; nt < NT; nt++)
            #pragma unroll
            for (int j = 0; j < 4; j++) acc[mt][nt][j] = 0.f;

    #pragma unroll
    for (int ks = 0; ks < 128; ks += 16) {
        uint32_t ah[2][4], al[2][4], bh[NT][2], bl[NT][2];
        #pragma unroll
        for (int mt = 0; mt < 2; mt++) {
            int rA = warp_m * 32 + mt * 16 + g;
            uint32_t o00 = ((rA)     * KP + ks + 2 * tg) * 2;
            uint32_t o10 = ((rA + 8) * KP + ks + 2 * tg) * 2;
            ah[mt][0] = *(uint32_t*)(smem + A_HI + o00);
            ah[mt][1] = *(uint32_t*)(smem + A_HI + o10);
            ah[mt][2] = *(uint32_t*)(smem + A_HI + o00 + 16);
            ah[mt][3] = *(uint32_t*)(smem + A_HI + o10 + 16);
            al[mt][0] = *(uint32_t*)(smem + A_LO + o00);
            al[mt][1] = *(uint32_t*)(smem + A_LO + o10);
            al[mt][2] = *(uint32_t*)(smem + A_LO + o00 + 16);
            al[mt][3] = *(uint32_t*)(smem + A_LO + o10 + 16);
        }
        #pragma unroll
        for (int nt = 0; nt < NT; nt++) {
            int nB = warp_n * (NT * 8) + nt * 8 + g;
            uint32_t ob = (nB * KP + ks + 2 * tg) * 2;
            bh[nt][0] = *(uint32_t*)(smem + W_HI + ob);
            bh[nt][1] = *(uint32_t*)(smem + W_HI + ob + 16);
            bl[nt][0] = *(uint32_t*)(smem + W_LO + ob);
            bl[nt][1] = *(uint32_t*)(smem + W_LO + ob + 16);
        }
        #pragma unroll
        for (int mt = 0; mt < 2; mt++)
            #pragma unroll
            for (int nt = 0; nt < NT; nt++) {
                MMA_BF16(acc[mt][nt], ah[mt], bh[nt]);
                MMA_BF16(acc[mt][nt], ah[mt], bl[nt]);
                MMA_BF16(acc[mt][nt], al[mt], bh[nt]);
            }
    }

    // epilogue: c0/c1 -> (row, col..col+1), c2/c3 -> (row+8, ...)
    #pragma unroll
    for (int mt = 0; mt < 2; mt++) {
        int row0 = row_base + warp_m * 32 + mt * 16 + g;
        #pragma unroll
        for (int nt = 0; nt < NT; nt++) {
            int col = warp_n * (NT * 8) + nt * 8 + 2 * tg;
            if (row0 < NN)
                *(float2*)(g_h + (long)row0 * BN + col) =
                    make_float2(acc[mt][nt][0], acc[mt][nt][1]);
            if (row0 + 8 < NN)
                *(float2*)(g_h + (long)(row0 + 8) * BN + col) =
                    make_float2(acc[mt][nt][2], acc[mt][nt][3]);
        }
    }
}

// ---------------- aggregation + fused BN stats (unchanged) ------------------
__global__ void __launch_bounds__(256)
k_agg128(const float* __restrict__ bias, float* __restrict__ outp, int statsoff) {
    __shared__ float4 s_sum[8][32];
    __shared__ float4 s_sq[8][32];
    int wlocal = threadIdx.x >> 5;
    int w = (blockIdx.x * 256 + threadIdx.x) >> 5;
    int lane = threadIdx.x & 31;
    const float4* h4 = (const float4*)g_h;
    float4 b4 = ((const float4*)bias)[lane];
    float4 sf = h4[w * 32 + lane];
    float di = g_dinv[w];
    float sc = di * di;
    float4 acc;
    acc.x = fmaf(sc, sf.x, b4.x);
    acc.y = fmaf(sc, sf.y, b4.y);
    acc.z = fmaf(sc, sf.z, b4.z);
    acc.w = fmaf(sc, sf.w, b4.w);
    int e = g_rowptr[w];
    const int end = g_rowptr[w + 1];
    for (; e + 2 <= end; e += 2) {
        int2 p0 = g_csr[e], p1 = g_csr[e + 1];
        float4 v0 = h4[p0.x * 32 + lane];
        float4 v1 = h4[p1.x * 32 + lane];
        float c0 = __int_as_float(p0.y), c1 = __int_as_float(p1.y);
        acc.x = fmaf(c0, v0.x, acc.x); acc.y = fmaf(c0, v0.y, acc.y);
        acc.z = fmaf(c0, v0.z, acc.z); acc.w = fmaf(c0, v0.w, acc.w);
        acc.x = fmaf(c1, v1.x, acc.x); acc.y = fmaf(c1, v1.y, acc.y);
        acc.z = fmaf(c1, v1.z, acc.z); acc.w = fmaf(c1, v1.w, acc.w);
    }
    if (e < end) {
        int2 p = g_csr[e];
        float4 v = h4[p.x * 32 + lane];
        float c = __int_as_float(p.y);
        acc.x = fmaf(c, v.x, acc.x); acc.y = fmaf(c, v.y, acc.y);
        acc.z = fmaf(c, v.z, acc.z); acc.w = fmaf(c, v.w, acc.w);
    }
    float4* o4 = (float4*)(outp ? outp : g_agg);
    o4[w * 32 + lane] = acc;

    if (statsoff >= 0) {
        s_sum[wlocal][lane] = acc;
        s_sq[wlocal][lane] = make_float4(acc.x * acc.x, acc.y * acc.y,
                                         acc.z * acc.z, acc.w * acc.w);
        __syncthreads();
        if (threadIdx.x < 128) {
            int c = threadIdx.x;
            int l = c >> 2, comp = c & 3;
            float s = 0.f, q = 0.f;
            #pragma unroll
            for (int ww = 0; ww < 8; ww++) {
                const float* ps = (const float*)&s_sum[ww][l];
                const float* pq = (const float*)&s_sq[ww][l];
                s += ps[comp];
                q += pq[comp];
            }
            atomicAdd(&g_stats[statsoff + c], s);
            atomicAdd(&g_stats[statsoff + 128 + c], q);
        }
    }
}

__global__ void __launch_bounds__(256)
k_agg64(const float* __restrict__ bias, float* __restrict__ outp) {
    int w = (blockIdx.x * 256 + threadIdx.x) >> 5;
    int lane = threadIdx.x & 31;
    const float2* h2 = (const float2*)g_h;
    float2 b2v = ((const float2*)bias)[lane];
    float2 sf = h2[w * 32 + lane];
    float di = g_dinv[w];
    float sc = di * di;
    float2 acc;
    acc.x = fmaf(sc, sf.x, b2v.x);
    acc.y = fmaf(sc, sf.y, b2v.y);
    int e = g_rowptr[w];
    const int end = g_rowptr[w + 1];
    for (; e + 2 <= end; e += 2) {
        int2 p0 = g_csr[e], p1 = g_csr[e + 1];
        float2 v0 = h2[p0.x * 32 + lane];
        float2 v1 = h2[p1.x * 32 + lane];
        float c0 = __int_as_float(p0.y), c1 = __int_as_float(p1.y);
        acc.x = fmaf(c0, v0.x, acc.x); acc.y = fmaf(c0, v0.y, acc.y);
        acc.x = fmaf(c1, v1.x, acc.x); acc.y = fmaf(c1, v1.y, acc.y);
    }
    if (e < end) {
        int2 p = g_csr[e];
        float2 v = h2[p.x * 32 + lane];
        float c = __int_as_float(p.y);
        acc.x = fmaf(c, v.x, acc.x); acc.y = fmaf(c, v.y, acc.y);
    }
    ((float2*)outp)[w * 32 + lane] = acc;
}

__global__ void k_bnfin(int soff, int coff, const float* __restrict__ gamma,
                        const float* __restrict__ beta) {
    int c = threadIdx.x;
    if (c < 128) {
        float mean = g_stats[soff + c] * (1.0f / NN);
        float var = g_stats[soff + 128 + c] * (1.0f / NN) - mean * mean;
        float rstd = rsqrtf(var + 1e-5f);
        float sc = rstd * gamma[c];
        g_stats[coff + c] = sc;
        g_stats[coff + 128 + c] = beta[c] - mean * sc;
    }
}

// ---------------- launch ----------------------------------------------------
extern "C" void kernel_launch(void* const* d_in, const int* in_sizes, int n_in,
                              void* d_out, int out_size) {
    const float* x   = (const float*)d_in[0];
    const int*   ei  = (const int*)d_in[1];
    const float* ew  = (const float*)d_in[2];
    const float* W1  = (const float*)d_in[3];
    const float* b1  = (const float*)d_in[4];
    const float* W2  = (const float*)d_in[5];
    const float* b2  = (const float*)d_in[6];
    const float* W3  = (const float*)d_in[7];
    const float* b3  = (const float*)d_in[8];
    const float* g1  = (const float*)d_in[9];
    const float* be1 = (const float*)d_in[10];
    const float* g2  = (const float*)d_in[11];
    const float* be2 = (const float*)d_in[12];
    const int* src = ei;
    const int* dst = ei + EE;
    float* out = (float*)d_out;

    const int agg_blocks = (NN * 32) / 256;     // 6250
    const int edge_blocks = (EE + 255) / 256;   // 3125
    const int gemm_blocks = (NN + 127) / 128;   // 391
    const int SM128 = 2 * 128 * 136 * 2 + 2 * 128 * 136 * 2;   // 139264
    const int SM64  = 2 * 128 * 136 * 2 + 2 * 64 * 136 * 2;    // 104448

    __nv_bfloat16* wblk_ptr = nullptr;
    cudaGetSymbolAddress((void**)&wblk_ptr, g_wblk);
    cudaFuncSetAttribute(k_gemm_mma<128>, cudaFuncAttributeMaxDynamicSharedMemorySize, SM128);
    cudaFuncSetAttribute(k_gemm_mma<64>,  cudaFuncAttributeMaxDynamicSharedMemorySize, SM64);

    // graph normalization + CSR + W prep
    k_prepw<<<160, 256>>>(W1, W2, W3);
    k_init<<<(NN + 255) / 256, 256>>>();
    k_count<<<edge_blocks, 256>>>(dst, ew);
    k_scan<<<1, 1024>>>();
    k_fill<<<edge_blocks, 256>>>(src, dst, ew);

    // layer 1
    k_gemm_mma<128><<<gemm_blocks, 256, SM128>>>(x, -1, wblk_ptr, wblk_ptr + 16384);
    k_agg128<<<agg_blocks, 256>>>(b1, nullptr, 0);
    k_bnfin<<<1, 128>>>(0, 512, g1, be1);

    // layer 2
    k_gemm_mma<128><<<gemm_blocks, 256, SM128>>>(nullptr, 512,
        wblk_ptr + 32768, wblk_ptr + 49152);
    k_agg128<<<agg_blocks, 256>>>(b2, nullptr, 256);
    k_bnfin<<<1, 128>>>(256, 768, g2, be2);

    // layer 3 (N = 64)
    k_gemm_mma<64><<<gemm_blocks, 256, SM64>>>(nullptr, 768,
        wblk_ptr + 65536, wblk_ptr + 73728);
    k_agg64<<<agg_blocks, 256>>>(b3, out);
}

// round 11
// speedup vs baseline: 1.3022x; 1.1555x over previous
#include <cuda_runtime.h>
#include <cuda_bf16.h>
#include <cstdint>

static constexpr int NN = 50000;
static constexpr int EE = 800000;
static constexpr int SCAN_BLKS = (NN + 1023) / 1024;   // 49
static constexpr int NPAD = NN + 256;                  // >= SCAN_BLKS*1024 = 50176

// ---------------- scratch (device globals; no allocation allowed) ----------
__device__ float g_h[NN * 128];      // pre-aggregation features (act(A) @ W)
__device__ float g_agg[NN * 128];    // aggregated features
__device__ float g_deg[NN];
__device__ float g_dinv[NN];
__device__ int   g_cnt[NPAD];        // padded so int4 scan tiles are in-bounds
__device__ int   g_rank[EE];
__device__ int   g_rowptr[NPAD];
__device__ int2  g_csr[EE];          // {src, __float_as_int(coef)}
__device__ float g_stats[1024];
__device__ int   g_blksum[SCAN_BLKS];
__device__ int   g_blkoff[SCAN_BLKS];
// W transposed [N][K] bf16 hi/lo: W1hi@0 W1lo@16384 W2hi@32768 W2lo@49152 W3hi@65536 W3lo@73728
__device__ __align__(16) __nv_bfloat16 g_wblk[81920];

__device__ __forceinline__ uint32_t packbf2(float x, float y) {
    __nv_bfloat162 p = __floats2bfloat162_rn(x, y);
    return *(uint32_t*)&p;
}

#define MMA_BF16(d, a, b) \
    asm volatile("mma.sync.aligned.m16n8k16.row.col.f32.bf16.bf16.f32 " \
        "{%0,%1,%2,%3}, {%4,%5,%6,%7}, {%8,%9}, {%0,%1,%2,%3};" \
        : "+f"((d)[0]), "+f"((d)[1]), "+f"((d)[2]), "+f"((d)[3]) \
        : "r"((a)[0]), "r"((a)[1]), "r"((a)[2]), "r"((a)[3]), "r"((b)[0]), "r"((b)[1]))

// ---------------- CSR build ------------------------------------------------
__global__ void k_init() {
    int i = blockIdx.x * 256 + threadIdx.x;
    if (i < NN) { g_deg[i] = 1.0f; }
    if (i < NPAD) g_cnt[i] = 0;
    if (i < 1024) g_stats[i] = 0.0f;
}
__global__ void k_count(const int* __restrict__ dst, const float* __restrict__ ew) {
    int e = blockIdx.x * 256 + threadIdx.x;
    if (e < EE) {
        int d = dst[e];
        g_rank[e] = atomicAdd(&g_cnt[d], 1);
        atomicAdd(&g_deg[d], ew[e]);
    }
}

// phase A: per-block exclusive prefix of g_cnt (1024 elems/block) + dinv
__global__ void k_scanA() {
    __shared__ int wsum[8];
    const int t = threadIdx.x;
    const int idx = blockIdx.x * 1024 + t * 4;
    int4 v = *(const int4*)&g_cnt[idx];          // padded: always in-bounds
    int s = v.x + v.y + v.z + v.w;
    int x = s;
    #pragma unroll
    for (int o = 1; o < 32; o <<= 1) {
        int tt = __shfl_up_sync(0xffffffffu, x, o);
        if ((t & 31) >= o) x += tt;
    }
    if ((t & 31) == 31) wsum[t >> 5] = x;
    __syncthreads();
    if (t < 8) {
        int w = wsum[t];
        #pragma unroll
        for (int o = 1; o < 8; o <<= 1) {
            int tt = __shfl_up_sync(0xffu, w, o);
            if (t >= o) w += tt;
        }
        wsum[t] = w;
    }
    __syncthreads();
    int woff = (t >= 32) ? wsum[(t >> 5) - 1] : 0;
    int ex = x - s + woff;                        // exclusive thread prefix
    g_rowptr[idx + 0] = ex;
    g_rowptr[idx + 1] = ex + v.x;
    g_rowptr[idx + 2] = ex + v.x + v.y;
    g_rowptr[idx + 3] = ex + v.x + v.y + v.z;
    if (t == 0) g_blksum[blockIdx.x] = wsum[7];
    #pragma unroll
    for (int j = 0; j < 4; j++) {
        int i = idx + j;
        if (i < NN) g_dinv[i] = rsqrtf(g_deg[i]);
    }
}

// phase B: scan the 49 block sums (1 tiny block, 64 threads)
__global__ void k_scanB() {
    __shared__ int sh[2];
    const int t = threadIdx.x;
    int v = (t < SCAN_BLKS) ? g_blksum[t] : 0;
    int x = v;
    #pragma unroll
    for (int o = 1; o < 32; o <<= 1) {
        int tt = __shfl_up_sync(0xffffffffu, x, o);
        if ((t & 31) >= o) x += tt;
    }
    if ((t & 31) == 31) sh[t >> 5] = x;
    __syncthreads();
    int woff = (t >= 32) ? sh[0] : 0;
    int incl = x + woff;
    if (t < SCAN_BLKS) g_blkoff[t] = incl - v;    // exclusive
    // NOTE: rowptr[NN] is produced naturally by scanC (zero-padded counts).
}

// phase C: add block offsets (also yields rowptr[NN] = EE via padding)
__global__ void k_scanC() {
    int off = g_blkoff[blockIdx.x];
    int idx = blockIdx.x * 1024 + threadIdx.x * 4;
    int4 v = *(const int4*)&g_rowptr[idx];
    v.x += off; v.y += off; v.z += off; v.w += off;
    *(int4*)&g_rowptr[idx] = v;
}

__global__ void k_fill(const int* __restrict__ src, const int* __restrict__ dst,
                       const float* __restrict__ ew) {
    int e = blockIdx.x * 256 + threadIdx.x;
    if (e < EE) {
        int s = src[e], d = dst[e];
        int pos = g_rowptr[d] + g_rank[e];
        float c = g_dinv[s] * ew[e] * g_dinv[d];
        g_csr[pos] = make_int2(s, __float_as_int(c));
    }
}

// ---------------- W prep: fp32 [K=128][N] -> transposed [N][128] bf16 hi/lo -
__device__ __forceinline__ void prep_one(const float* W, int N, int t,
                                         __nv_bfloat16* hi_d, __nv_bfloat16* lo_d) {
    int k = t / N, n = t % N;
    float w = W[k * N + n];
    __nv_bfloat16 h = __float2bfloat16(w);
    __nv_bfloat16 l = __float2bfloat16(w - __bfloat162float(h));
    hi_d[n * 128 + k] = h;
    lo_d[n * 128 + k] = l;
}
__global__ void k_prepw(const float* __restrict__ W1, const float* __restrict__ W2,
                        const float* __restrict__ W3) {
    int b = blockIdx.x, tid = threadIdx.x;
    if (b < 64)        prep_one(W1, 128, b * 256 + tid,         g_wblk,         g_wblk + 16384);
    else if (b < 128)  prep_one(W2, 128, (b - 64) * 256 + tid,  g_wblk + 32768, g_wblk + 49152);
    else               prep_one(W3, 64,  (b - 128) * 256 + tid, g_wblk + 65536, g_wblk + 73728);
}

// ---------------- GEMM: g_h = act(A) @ W via mma.sync bf16 3-term -----------
template <int BN>
__global__ void __launch_bounds__(256, 1)
k_gemm_mma(const float* __restrict__ Aext, int coff,
           const __nv_bfloat16* __restrict__ whi, const __nv_bfloat16* __restrict__ wlo) {
    constexpr int KP = 136;
    constexpr int NT = BN / 16;
    constexpr int A_HI = 0;
    constexpr int A_LO = 128 * KP * 2;
    constexpr int W_HI = 2 * 128 * KP * 2;
    constexpr int W_LO = W_HI + BN * KP * 2;
    extern __shared__ char smem[];
    const float* A = Aext ? Aext : g_agg;
    const int tid = threadIdx.x;
    const int wid = tid >> 5, lane = tid & 31;
    const int warp_m = wid & 3, warp_n = wid >> 2;
    const int row_base = blockIdx.x * 128;

    for (int i = tid; i < 128 * 32; i += 256) {
        int r = i >> 5;
        int c = (i & 31) << 2;
        int gr = row_base + r;
        float4 v = make_float4(0.f, 0.f, 0.f, 0.f);
        if (gr < NN) {
            v = *(const float4*)(A + (long)gr * 128 + c);
            if (coff >= 0) {
                float4 sc = *(const float4*)(g_stats + coff + c);
                float4 sh = *(const float4*)(g_stats + coff + 128 + c);
                v.x = fmaxf(0.f, fmaf(v.x, sc.x, sh.x));
                v.y = fmaxf(0.f, fmaf(v.y, sc.y, sh.y));
                v.z = fmaxf(0.f, fmaf(v.z, sc.z, sh.z));
                v.w = fmaxf(0.f, fmaf(v.w, sc.w, sh.w));
            }
        }
        float hx = __bfloat162float(__float2bfloat16(v.x));
        float hy = __bfloat162float(__float2bfloat16(v.y));
        float hz = __bfloat162float(__float2bfloat16(v.z));
        float hw = __bfloat162float(__float2bfloat16(v.w));
        uint32_t off = (r * KP + c) * 2;
        *(uint32_t*)(smem + A_HI + off)     = packbf2(hx, hy);
        *(uint32_t*)(smem + A_HI + off + 4) = packbf2(hz, hw);
        *(uint32_t*)(smem + A_LO + off)     = packbf2(v.x - hx, v.y - hy);
        *(uint32_t*)(smem + A_LO + off + 4) = packbf2(v.z - hz, v.w - hw);
    }
    for (int i = tid; i < BN * 16; i += 256) {
        int n = i >> 4;
        int k = (i & 15) << 3;
        uint32_t off = (n * KP + k) * 2;
        *(uint4*)(smem + W_HI + off) = ((const uint4*)whi)[i];
        *(uint4*)(smem + W_LO + off) = ((const uint4*)wlo)[i];
    }
    __syncthreads();

    const int g = lane >> 2, tg = lane & 3;
    float acc[2][NT][4];
    #pragma unroll
    for (int mt = 0; mt < 2; mt++)
        #pragma unroll
        for (int nt = 0; nt < NT; nt++)
            #pragma unroll
            for (int j = 0; j < 4; j++) acc[mt][nt][j] = 0.f;

    #pragma unroll
    for (int ks = 0; ks < 128; ks += 16) {
        uint32_t ah[2][4], al[2][4], bh[NT][2], bl[NT][2];
        #pragma unroll
        for (int mt = 0; mt < 2; mt++) {
            int rA = warp_m * 32 + mt * 16 + g;
            uint32_t o00 = ((rA)     * KP + ks + 2 * tg) * 2;
            uint32_t o10 = ((rA + 8) * KP + ks + 2 * tg) * 2;
            ah[mt][0] = *(uint32_t*)(smem + A_HI + o00);
            ah[mt][1] = *(uint32_t*)(smem + A_HI + o10);
            ah[mt][2] = *(uint32_t*)(smem + A_HI + o00 + 16);
            ah[mt][3] = *(uint32_t*)(smem + A_HI + o10 + 16);
            al[mt][0] = *(uint32_t*)(smem + A_LO + o00);
            al[mt][1] = *(uint32_t*)(smem + A_LO + o10);
            al[mt][2] = *(uint32_t*)(smem + A_LO + o00 + 16);
            al[mt][3] = *(uint32_t*)(smem + A_LO + o10 + 16);
        }
        #pragma unroll
        for (int nt = 0; nt < NT; nt++) {
            int nB = warp_n * (NT * 8) + nt * 8 + g;
            uint32_t ob = (nB * KP + ks + 2 * tg) * 2;
            bh[nt][0] = *(uint32_t*)(smem + W_HI + ob);
            bh[nt][1] = *(uint32_t*)(smem + W_HI + ob + 16);
            bl[nt][0] = *(uint32_t*)(smem + W_LO + ob);
            bl[nt][1] = *(uint32_t*)(smem + W_LO + ob + 16);
        }
        #pragma unroll
        for (int mt = 0; mt < 2; mt++)
            #pragma unroll
            for (int nt = 0; nt < NT; nt++) {
                MMA_BF16(acc[mt][nt], ah[mt], bh[nt]);
                MMA_BF16(acc[mt][nt], ah[mt], bl[nt]);
                MMA_BF16(acc[mt][nt], al[mt], bh[nt]);
            }
    }

    #pragma unroll
    for (int mt = 0; mt < 2; mt++) {
        int row0 = row_base + warp_m * 32 + mt * 16 + g;
        #pragma unroll
        for (int nt = 0; nt < NT; nt++) {
            int col = warp_n * (NT * 8) + nt * 8 + 2 * tg;
            if (row0 < NN)
                *(float2*)(g_h + (long)row0 * BN + col) =
                    make_float2(acc[mt][nt][0], acc[mt][nt][1]);
            if (row0 + 8 < NN)
                *(float2*)(g_h + (long)(row0 + 8) * BN + col) =
                    make_float2(acc[mt][nt][2], acc[mt][nt][3]);
        }
    }
}

// ---------------- aggregation + fused BN stats ------------------------------
__global__ void __launch_bounds__(256)
k_agg128(const float* __restrict__ bias, float* __restrict__ outp, int statsoff) {
    __shared__ float4 s_sum[8][32];
    __shared__ float4 s_sq[8][32];
    int wlocal = threadIdx.x >> 5;
    int w = (blockIdx.x * 256 + threadIdx.x) >> 5;
    int lane = threadIdx.x & 31;
    const float4* h4 = (const float4*)g_h;
    float4 b4 = ((const float4*)bias)[lane];
    float4 sf = h4[w * 32 + lane];
    float di = g_dinv[w];
    float sc = di * di;
    float4 acc;
    acc.x = fmaf(sc, sf.x, b4.x);
    acc.y = fmaf(sc, sf.y, b4.y);
    acc.z = fmaf(sc, sf.z, b4.z);
    acc.w = fmaf(sc, sf.w, b4.w);
    int e = g_rowptr[w];
    const int end = g_rowptr[w + 1];
    for (; e + 2 <= end; e += 2) {
        int2 p0 = g_csr[e], p1 = g_csr[e + 1];
        float4 v0 = h4[p0.x * 32 + lane];
        float4 v1 = h4[p1.x * 32 + lane];
        float c0 = __int_as_float(p0.y), c1 = __int_as_float(p1.y);
        acc.x = fmaf(c0, v0.x, acc.x); acc.y = fmaf(c0, v0.y, acc.y);
        acc.z = fmaf(c0, v0.z, acc.z); acc.w = fmaf(c0, v0.w, acc.w);
        acc.x = fmaf(c1, v1.x, acc.x); acc.y = fmaf(c1, v1.y, acc.y);
        acc.z = fmaf(c1, v1.z, acc.z); acc.w = fmaf(c1, v1.w, acc.w);
    }
    if (e < end) {
        int2 p = g_csr[e];
        float4 v = h4[p.x * 32 + lane];
        float c = __int_as_float(p.y);
        acc.x = fmaf(c, v.x, acc.x); acc.y = fmaf(c, v.y, acc.y);
        acc.z = fmaf(c, v.z, acc.z); acc.w = fmaf(c, v.w, acc.w);
    }
    float4* o4 = (float4*)(outp ? outp : g_agg);
    o4[w * 32 + lane] = acc;

    if (statsoff >= 0) {
        s_sum[wlocal][lane] = acc;
        s_sq[wlocal][lane] = make_float4(acc.x * acc.x, acc.y * acc.y,
                                         acc.z * acc.z, acc.w * acc.w);
        __syncthreads();
        if (threadIdx.x < 128) {
            int c = threadIdx.x;
            int l = c >> 2, comp = c & 3;
            float s = 0.f, q = 0.f;
            #pragma unroll
            for (int ww = 0; ww < 8; ww++) {
                const float* ps = (const float*)&s_sum[ww][l];
                const float* pq = (const float*)&s_sq[ww][l];
                s += ps[comp];
                q += pq[comp];
            }
            atomicAdd(&g_stats[statsoff + c], s);
            atomicAdd(&g_stats[statsoff + 128 + c], q);
        }
    }
}

__global__ void __launch_bounds__(256)
k_agg64(const float* __restrict__ bias, float* __restrict__ outp) {
    int w = (blockIdx.x * 256 + threadIdx.x) >> 5;
    int lane = threadIdx.x & 31;
    const float2* h2 = (const float2*)g_h;
    float2 b2v = ((const float2*)bias)[lane];
    float2 sf = h2[w * 32 + lane];
    float di = g_dinv[w];
    float sc = di * di;
    float2 acc;
    acc.x = fmaf(sc, sf.x, b2v.x);
    acc.y = fmaf(sc, sf.y, b2v.y);
    int e = g_rowptr[w];
    const int end = g_rowptr[w + 1];
    for (; e + 2 <= end; e += 2) {
        int2 p0 = g_csr[e], p1 = g_csr[e + 1];
        float2 v0 = h2[p0.x * 32 + lane];
        float2 v1 = h2[p1.x * 32 + lane];
        float c0 = __int_as_float(p0.y), c1 = __int_as_float(p1.y);
        acc.x = fmaf(c0, v0.x, acc.x); acc.y = fmaf(c0, v0.y, acc.y);
        acc.x = fmaf(c1, v1.x, acc.x); acc.y = fmaf(c1, v1.y, acc.y);
    }
    if (e < end) {
        int2 p = g_csr[e];
        float2 v = h2[p.x * 32 + lane];
        float c = __int_as_float(p.y);
        acc.x = fmaf(c, v.x, acc.x); acc.y = fmaf(c, v.y, acc.y);
    }
    ((float2*)outp)[w * 32 + lane] = acc;
}

__global__ void k_bnfin(int soff, int coff, const float* __restrict__ gamma,
                        const float* __restrict__ beta) {
    int c = threadIdx.x;
    if (c < 128) {
        float mean = g_stats[soff + c] * (1.0f / NN);
        float var = g_stats[soff + 128 + c] * (1.0f / NN) - mean * mean;
        float rstd = rsqrtf(var + 1e-5f);
        float sc = rstd * gamma[c];
        g_stats[coff + c] = sc;
        g_stats[coff + 128 + c] = beta[c] - mean * sc;
    }
}

// ---------------- launch ----------------------------------------------------
extern "C" void kernel_launch(void* const* d_in, const int* in_sizes, int n_in,
                              void* d_out, int out_size) {
    const float* x   = (const float*)d_in[0];
    const int*   ei  = (const int*)d_in[1];
    const float* ew  = (const float*)d_in[2];
    const float* W1  = (const float*)d_in[3];
    const float* b1  = (const float*)d_in[4];
    const float* W2  = (const float*)d_in[5];
    const float* b2  = (const float*)d_in[6];
    const float* W3  = (const float*)d_in[7];
    const float* b3  = (const float*)d_in[8];
    const float* g1  = (const float*)d_in[9];
    const float* be1 = (const float*)d_in[10];
    const float* g2  = (const float*)d_in[11];
    const float* be2 = (const float*)d_in[12];
    const int* src = ei;
    const int* dst = ei + EE;
    float* out = (float*)d_out;

    const int agg_blocks = (NN * 32) / 256;     // 6250
    const int edge_blocks = (EE + 255) / 256;   // 3125
    const int gemm_blocks = (NN + 127) / 128;   // 391
    const int SM128 = 2 * 128 * 136 * 2 + 2 * 128 * 136 * 2;   // 139264
    const int SM64  = 2 * 128 * 136 * 2 + 2 * 64 * 136 * 2;    // 104448

    __nv_bfloat16* wblk_ptr = nullptr;
    cudaGetSymbolAddress((void**)&wblk_ptr, g_wblk);
    cudaFuncSetAttribute(k_gemm_mma<128>, cudaFuncAttributeMaxDynamicSharedMemorySize, SM128);
    cudaFuncSetAttribute(k_gemm_mma<64>,  cudaFuncAttributeMaxDynamicSharedMemorySize, SM64);

    // graph normalization + CSR + W prep
    k_prepw<<<160, 256>>>(W1, W2, W3);
    k_init<<<(NPAD + 255) / 256, 256>>>();
    k_count<<<edge_blocks, 256>>>(dst, ew);
    k_scanA<<<SCAN_BLKS, 256>>>();
    k_scanB<<<1, 64>>>();
    k_scanC<<<SCAN_BLKS, 256>>>();
    k_fill<<<edge_blocks, 256>>>(src, dst, ew);

    // layer 1
    k_gemm_mma<128><<<gemm_blocks, 256, SM128>>>(x, -1, wblk_ptr, wblk_ptr + 16384);
    k_agg128<<<agg_blocks, 256>>>(b1, nullptr, 0);
    k_bnfin<<<1, 128>>>(0, 512, g1, be1);

    // layer 2
    k_gemm_mma<128><<<gemm_blocks, 256, SM128>>>(nullptr, 512,
        wblk_ptr + 32768, wblk_ptr + 49152);
    k_agg128<<<agg_blocks, 256>>>(b2, nullptr, 256);
    k_bnfin<<<1, 128>>>(256, 768, g2, be2);

    // layer 3 (N = 64)
    k_gemm_mma<64><<<gemm_blocks, 256, SM64>>>(nullptr, 768,
        wblk_ptr + 65536, wblk_ptr + 73728);
    k_agg64<<<agg_blocks, 256>>>(b3, out);
}